// round 4
// baseline (speedup 1.0000x reference)
#include <cuda_runtime.h>
#include <math.h>

#define MAXN   100000
#define FIN    128
#define HIDD   16
#define COUT   10
#define CPAD   12          // layer-2 aggregation row: 12 floats (48B)
#define P1W    32          // packed layer-1 row: h0[0..15] | d1[16..31]  (128B line)
#define P2W    32          // packed layer-2 row: h0b[0..11] | d2[16..27] (128B line)

// -------- device scratch (static: no allocation allowed) --------
__device__ __align__(128) float g_p1 [MAXN * P1W];  // packed h0|d1
__device__ float g_r1 [MAXN * HIDD];                // x @ root1 + b1
__device__ float g_A1 [MAXN * HIDD];                // edge aggregation layer 1
__device__ __align__(128) float g_p2 [MAXN * P2W];  // packed h0b|d2
__device__ float g_r2 [MAXN * CPAD];                // h @ root2 + b2
__device__ float g_A2 [MAXN * CPAD];                // edge aggregation layer 2
__device__ float g_deg[MAXN];
__device__ int   g_is64;

// -------- detect int64 vs int32 edge_index (warp-parallel) --------
__global__ void detect_idx_kernel(const long long* __restrict__ ei, int n) {
    int lane = threadIdx.x;
    long long v = ei[lane];
    unsigned ok = __ballot_sync(0xFFFFFFFFu, v >= 0 && v < (long long)n);
    if (lane == 0) g_is64 = (ok == 0xFFFFFFFFu) ? 1 : 0;
}

// -------- layer-1 node GEMM: 48 columns of 128-dim dots --------
// Writes packed p1 row, r1; zeroes A1 and deg (fused init).
__global__ void __launch_bounds__(256)
gemm1_kernel(const float* __restrict__ x,
             const float* __restrict__ W1,
             const float* __restrict__ root1,
             const float* __restrict__ b1,
             int n) {
    __shared__ float sW[48 * FIN];     // 24 KB: [j][k] layout
    for (int i = threadIdx.x; i < 48 * FIN; i += blockDim.x) {
        int j = i >> 7;      // 0..47
        int k = i & 127;     // 0..127
        float v;
        if (j < 16)       v = W1[k * 16 + j];
        else if (j < 32)  v = W1[2048 + k * 16 + (j - 16)] - W1[k * 16 + (j - 16)];
        else              v = root1[k * 16 + (j - 32)];
        sW[j * FIN + k] = v;
    }
    __syncthreads();

    int node = blockIdx.x * blockDim.x + threadIdx.x;
    if (node >= n) return;

    const float4* xr  = (const float4*)(x + (size_t)node * FIN);
    const float4* sW4 = (const float4*)sW;

    float acc[48];
#pragma unroll
    for (int j = 0; j < 48; j++) acc[j] = 0.f;

#pragma unroll 4
    for (int kc = 0; kc < FIN / 4; kc++) {
        float4 xv = xr[kc];
#pragma unroll
        for (int j = 0; j < 48; j++) {
            float4 wv = sW4[j * (FIN / 4) + kc];   // uniform across warp -> smem broadcast
            acc[j] += xv.x * wv.x + xv.y * wv.y + xv.z * wv.z + xv.w * wv.w;
        }
    }

    float4* p1 = (float4*)(g_p1 + (size_t)node * P1W);
    float4* A1 = (float4*)(g_A1 + (size_t)node * HIDD);
    float*  r1 = g_r1 + (size_t)node * HIDD;
#pragma unroll
    for (int q = 0; q < 8; q++)     // h0 then d1, packed
        p1[q] = make_float4(acc[q*4], acc[q*4+1], acc[q*4+2], acc[q*4+3]);
#pragma unroll
    for (int j = 0; j < 16; j++) r1[j] = acc[32 + j] + b1[j];
#pragma unroll
    for (int q = 0; q < 4; q++) A1[q] = make_float4(0.f, 0.f, 0.f, 0.f);
    g_deg[node] = 0.f;
}

// -------- vector reduction helper --------
__device__ __forceinline__ void red_add_v4(float* p, float4 v) {
    asm volatile("red.global.add.v4.f32 [%0], {%1, %2, %3, %4};"
                 :: "l"(__cvta_generic_to_global(p)),
                    "f"(v.x), "f"(v.y), "f"(v.z), "f"(v.w)
                 : "memory");
}

// -------- layer-1 edge pass: gather packed row, FMA, scatter-add --------
__global__ void __launch_bounds__(256)
edge1_kernel(const long long* __restrict__ ei,
             const float* __restrict__ ea, int E) {
    int e = blockIdx.x * blockDim.x + threadIdx.x;
    if (e >= E) return;
    const int is64 = g_is64;
    int s, t;
    if (is64) {
        s = (int)ei[e];
        t = (int)ei[(size_t)E + e];
    } else {
        const int* ei32 = (const int*)ei;
        s = ei32[e];
        t = ei32[(size_t)E + e];
    }
    float w = ea[e];
    const float4* row = (const float4*)(g_p1 + (size_t)s * P1W);  // one 128B line
    float* out = g_A1 + (size_t)t * HIDD;
#pragma unroll
    for (int q = 0; q < 4; q++) {
        float4 av = row[q];       // h0
        float4 bv = row[q + 4];   // d1
        float4 m;
        m.x = fmaf(w, bv.x, av.x);
        m.y = fmaf(w, bv.y, av.y);
        m.z = fmaf(w, bv.z, av.z);
        m.w = fmaf(w, bv.w, av.w);
        red_add_v4(out + q * 4, m);
    }
    atomicAdd(&g_deg[t], 1.0f);
}

// -------- fused: h = elu(A1/deg + r1); then layer-2 node GEMM --------
__global__ void __launch_bounds__(256)
ng2_kernel(const float* __restrict__ W2,
           const float* __restrict__ root2,
           const float* __restrict__ b2,
           int n) {
    __shared__ float sW[30 * HIDD];    // [j][k]
    __shared__ float sB[COUT];
    for (int i = threadIdx.x; i < 30 * HIDD; i += blockDim.x) {
        int j = i >> 4;      // 0..29
        int k = i & 15;
        float v;
        if (j < 10)       v = W2[k * 10 + j];
        else if (j < 20)  v = W2[160 + k * 10 + (j - 10)] - W2[k * 10 + (j - 10)];
        else              v = root2[k * 10 + (j - 20)];
        sW[j * HIDD + k] = v;
    }
    if (threadIdx.x < COUT) sB[threadIdx.x] = b2[threadIdx.x];
    __syncthreads();

    int node = blockIdx.x * blockDim.x + threadIdx.x;
    if (node >= n) return;

    float dg = fmaxf(g_deg[node], 1.0f);
    const float4* A1 = (const float4*)(g_A1 + (size_t)node * HIDD);
    const float4* r1 = (const float4*)(g_r1 + (size_t)node * HIDD);

    float h[16];
#pragma unroll
    for (int q = 0; q < 4; q++) {
        float4 av = A1[q];
        float4 rv = r1[q];
        float v0 = av.x / dg + rv.x;
        float v1 = av.y / dg + rv.y;
        float v2 = av.z / dg + rv.z;
        float v3 = av.w / dg + rv.w;
        h[q*4+0] = (v0 > 0.f) ? v0 : expm1f(v0);
        h[q*4+1] = (v1 > 0.f) ? v1 : expm1f(v1);
        h[q*4+2] = (v2 > 0.f) ? v2 : expm1f(v2);
        h[q*4+3] = (v3 > 0.f) ? v3 : expm1f(v3);
    }

    float acc[30];
#pragma unroll
    for (int j = 0; j < 30; j++) acc[j] = 0.f;
#pragma unroll
    for (int k = 0; k < HIDD; k++) {
        float hv = h[k];
#pragma unroll
        for (int j = 0; j < 30; j++)
            acc[j] = fmaf(hv, sW[j * HIDD + k], acc[j]);
    }

    // packed p2 row: h0b at [0..11] (pads 0), d2 at [16..27] (pads 0)
    float p2row[P2W];
#pragma unroll
    for (int i = 0; i < P2W; i++) p2row[i] = 0.f;
#pragma unroll
    for (int c = 0; c < COUT; c++) {
        p2row[c]      = acc[c];
        p2row[16 + c] = acc[10 + c];
    }
    float4* p2 = (float4*)(g_p2 + (size_t)node * P2W);
#pragma unroll
    for (int q = 0; q < 8; q++)
        p2[q] = make_float4(p2row[q*4], p2row[q*4+1], p2row[q*4+2], p2row[q*4+3]);

    float* r2 = g_r2 + (size_t)node * CPAD;
    float* A2 = g_A2 + (size_t)node * CPAD;
#pragma unroll
    for (int c = 0; c < COUT; c++) r2[c] = acc[20 + c] + sB[c];
    r2[10] = 0.f; r2[11] = 0.f;
#pragma unroll
    for (int c = 0; c < CPAD; c++) A2[c] = 0.f;
}

// -------- layer-2 edge pass (packed 128B source row) --------
__global__ void __launch_bounds__(256)
edge2_kernel(const long long* __restrict__ ei,
             const float* __restrict__ ea, int E) {
    int e = blockIdx.x * blockDim.x + threadIdx.x;
    if (e >= E) return;
    const int is64 = g_is64;
    int s, t;
    if (is64) {
        s = (int)ei[e];
        t = (int)ei[(size_t)E + e];
    } else {
        const int* ei32 = (const int*)ei;
        s = ei32[e];
        t = ei32[(size_t)E + e];
    }
    float w = ea[e];
    const float4* row = (const float4*)(g_p2 + (size_t)s * P2W);  // one 128B line
    float* out = g_A2 + (size_t)t * CPAD;
#pragma unroll
    for (int q = 0; q < 3; q++) {
        float4 av = row[q];       // h0b
        float4 bv = row[q + 4];   // d2
        float4 m;
        m.x = fmaf(w, bv.x, av.x);
        m.y = fmaf(w, bv.y, av.y);
        m.z = fmaf(w, bv.z, av.z);
        m.w = fmaf(w, bv.w, av.w);
        red_add_v4(out + q * 4, m);
    }
}

// -------- final epilogue: out = A2/deg + r2 (unpadded 10-wide output) --------
// blockDim=320: each block covers exactly 32 nodes; i/COUT stays cheap and
// stores remain fully coalesced across the 10-wide rows.
__global__ void __launch_bounds__(320)
node2_kernel(float* __restrict__ out, int n) {
    int i = blockIdx.x * blockDim.x + threadIdx.x;
    if (i >= n * COUT) return;
    int node = i / COUT;
    int c    = i - node * COUT;
    float dg = fmaxf(g_deg[node], 1.0f);
    out[i] = g_A2[(size_t)node * CPAD + c] / dg + g_r2[(size_t)node * CPAD + c];
}

extern "C" void kernel_launch(void* const* d_in, const int* in_sizes, int n_in,
                              void* d_out, int out_size) {
    const float*     x     = (const float*)d_in[0];
    const long long* ei    = (const long long*)d_in[1];
    const float*     ea    = (const float*)d_in[2];
    const float*     W1    = (const float*)d_in[3];
    const float*     root1 = (const float*)d_in[4];
    const float*     b1    = (const float*)d_in[5];
    const float*     W2    = (const float*)d_in[6];
    const float*     root2 = (const float*)d_in[7];
    const float*     b2    = (const float*)d_in[8];
    float* out = (float*)d_out;

    int n = in_sizes[0] / FIN;       // 100000
    int E = in_sizes[2];             // 1600000 (edge_attr is (E,1))

    detect_idx_kernel<<<1, 32>>>(ei, n);
    gemm1_kernel<<<(n + 255) / 256, 256>>>(x, W1, root1, b1, n);
    edge1_kernel<<<(E + 255) / 256, 256>>>(ei, ea, E);
    ng2_kernel<<<(n + 255) / 256, 256>>>(W2, root2, b2, n);
    edge2_kernel<<<(E + 255) / 256, 256>>>(ei, ea, E);
    node2_kernel<<<(n * COUT + 319) / 320, 320>>>(out, n);
}